// round 14
// baseline (speedup 1.0000x reference)
#include <cuda_runtime.h>
#include <cuda_fp16.h>
#include <math.h>
#include <cstdint>

// ---------------- problem constants ----------------------------------------
#define NB    8
#define Cc    256
#define HW    961
#define Mrows 7688
#define MP    7808          // padded M = 61*128
#define HID   512
#define OUTF  256

// ---------------- scratch (device globals; zero-initialized) ----------------
__device__ float    g_S0  [NB * Cc];
__device__ uint32_t g_YP  [MP * (Cc / 2)];     // LOCAL agg, packed fp16x2 [m][k2]
__device__ uint32_t g_W1hP[HID * (Cc / 2)];
__device__ uint32_t g_W2hP[OUTF * (HID / 2)];
__device__ uint32_t g_H1P [MP * (HID / 2)];    // H1 packed fp16x2 [m][k2]
__device__ float    g_P   [NB * 31 * HID];
__device__ float    g_S1B [NB * HID];          // per-sample sums [b][k]
__device__ float    g_T1  [NB * HID];          // S-term epilogue corrections
__device__ float    g_T2  [NB * OUTF];

// ---------------- helpers ----------------------------------------------------
__device__ __forceinline__ uint32_t smem_u32(const void* p) {
    uint32_t a;
    asm("{ .reg .u64 t; cvta.to.shared.u64 t, %1; cvt.u32.u64 %0, t; }"
        : "=r"(a) : "l"(p));
    return a;
}

__device__ __forceinline__ float dinv_of(int b) {
    int deg = (b == 0 || b == NB - 1) ? 963 : 964;
    return 1.0f / sqrtf((float)deg);
}

__device__ __forceinline__ uint32_t f16x2_pack(float v0, float v1) {
    __half2 h = __floats2half2_rn(v0, v1);
    return *(uint32_t*)&h;
}

// deterministic float atomic max (dst inited to -inf)
__device__ __forceinline__ void atomicMaxF(float* addr, float v) {
    if (v >= 0.f) atomicMax((int*)addr, __float_as_int(v));
    else          atomicMin((unsigned int*)addr, (unsigned int)__float_as_int(v));
}

#define MMA_F16(d, a0, a1, a2, a3, b0, b1) \
    asm volatile("mma.sync.aligned.m16n8k16.row.col.f32.f16.f16.f32 " \
                 "{%0,%1,%2,%3},{%4,%5,%6,%7},{%8,%9},{%0,%1,%2,%3};" \
                 : "+f"((d)[0]), "+f"((d)[1]), "+f"((d)[2]), "+f"((d)[3]) \
                 : "r"(a0), "r"(a1), "r"(a2), "r"(a3), "r"(b0), "r"(b1))

#define LDSM_X4(r0, r1, r2, r3, addr) \
    asm volatile("ldmatrix.sync.aligned.m8n8.x4.shared.b16 {%0,%1,%2,%3}, [%4];" \
                 : "=r"(r0), "=r"(r1), "=r"(r2), "=r"(r3) : "r"(addr))

#define CP_ASYNC16(dst32, src) \
    asm volatile("cp.async.cg.shared.global [%0], [%1], 16;" :: "r"(dst32), "l"(src))
#define CP_COMMIT()  asm volatile("cp.async.commit_group;" ::: "memory")
#define CP_WAIT1()   asm volatile("cp.async.wait_group 1;" ::: "memory")

// ---------------- fused prep kernel (one launch, 5 jobs) ----------------------
#define PREP_BLOCKS 3409
__global__ void prep_fused(const float* __restrict__ x,
                           const float* __restrict__ W1,
                           const float* __restrict__ W2,
                           float* __restrict__ S0,
                           uint32_t* __restrict__ YP,
                           uint32_t* __restrict__ W1h,
                           uint32_t* __restrict__ W2h,
                           float* __restrict__ out) {
    __shared__ float red[8];
    const int blk = blockIdx.x;
    const int tid = threadIdx.x;

    if (blk < 992) {
        int mblk = blk % 31, cq = blk / 31;
        int m = mblk * 256 + tid;
        if (m >= Mrows) return;
        int b = m / HW, p = m - b * HW;
        float db = dinv_of(b);
        float c0 = db * db;
        float cm = (b > 0)      ? db * dinv_of(b - 1) : 0.f;
        float cp = (b < NB - 1) ? db * dinv_of(b + 1) : 0.f;
        uint32_t w[4];
        #pragma unroll
        for (int j = 0; j < 4; j++) {
            float v2[2];
            #pragma unroll
            for (int e = 0; e < 2; e++) {
                int c = cq * 8 + j * 2 + e;
                size_t xi = (size_t)(b * Cc + c) * HW + p;
                float vv = c0 * __ldg(&x[xi]);
                if (b > 0)      vv += cm * __ldg(&x[xi - (size_t)Cc * HW]);
                if (b < NB - 1) vv += cp * __ldg(&x[xi + (size_t)Cc * HW]);
                v2[e] = vv;
            }
            w[j] = f16x2_pack(v2[0], v2[1]);
        }
        *(uint4*)(YP + (size_t)m * (Cc / 2) + cq * 4) = make_uint4(w[0], w[1], w[2], w[3]);
    } else if (blk < 3040) {
        int bc = blk - 992;
        const float* src = x + (size_t)bc * HW;
        float s = 0.f;
        for (int p = tid; p < HW; p += 256) s += src[p];
        #pragma unroll
        for (int off = 16; off; off >>= 1) s += __shfl_down_sync(0xffffffffu, s, off);
        if ((tid & 31) == 0) red[tid >> 5] = s;
        __syncthreads();
        if (tid < 8) {
            s = red[tid];
            #pragma unroll
            for (int off = 4; off; off >>= 1) s += __shfl_down_sync(0xffu, s, off);
            if (tid == 0) S0[bc] = s;
        }
    } else if (blk < 3168) {
        bool isW1 = blk < 3104;
        const float* W = isW1 ? W1 : W2;
        uint32_t* Wh = isW1 ? W1h : W2h;
        int base = ((blk - (isW1 ? 3040 : 3104)) * 256 + tid) * 4;   // word idx
        float4 a = ((const float4*)W)[base / 2];
        float4 c = ((const float4*)W)[base / 2 + 1];
        Wh[base]     = f16x2_pack(a.x, a.y);
        Wh[base + 1] = f16x2_pack(a.z, a.w);
        Wh[base + 2] = f16x2_pack(c.x, c.y);
        Wh[base + 3] = f16x2_pack(c.z, c.w);
    } else {
        int i4 = (blk - 3168) * 256 + tid;
        if (i4 < OUTF * HW / 4) {
            float ninf = __int_as_float(0xFF800000);
            ((float4*)out)[i4] = make_float4(ninf, ninf, ninf, ninf);
        }
    }
}

// ---------------- tiny S-term GEMM: T[b][n] = c0_b * sum_k S[b,k] W[n,k] -----
template<int K>
__global__ void t_small(const float* __restrict__ S, const float* __restrict__ W,
                        float* __restrict__ T, int N) {
    int w = threadIdx.x >> 5, lane = threadIdx.x & 31;
    int idx = blockIdx.x * 8 + w;
    if (idx >= N * NB) return;
    int n = idx >> 3, b = idx & 7;
    float s = 0.f;
    for (int k = lane; k < K; k += 32)
        s += __ldg(&S[b * K + k]) * __ldg(&W[n * K + k]);
    #pragma unroll
    for (int off = 16; off; off >>= 1) s += __shfl_down_sync(0xffffffffu, s, off);
    if (lane == 0) {
        float db = dinv_of(b);
        T[b * N + n] = db * db * s;
    }
}

// ---------------- per-sample sums of H1P (8x31 grid, 31 rows/chunk) ----------
__global__ void sum_h_part(const uint32_t* __restrict__ H1P, float* __restrict__ P) {
    int b = blockIdx.x, chunk = blockIdx.y;   // 8 x 31
    int t = threadIdx.x;                      // k2 word 0..255
    int p0 = chunk * 31;
    float s0 = 0.f, s1 = 0.f;
    #pragma unroll 4
    for (int p = p0; p < p0 + 31; p++) {
        uint32_t w = __ldg(&H1P[(size_t)(b * HW + p) * (HID / 2) + t]);
        float2 f = __half22float2(*(__half2*)&w);
        s0 += f.x; s1 += f.y;
    }
    P[((size_t)(b * 31 + chunk)) * HID + 2 * t]     = s0;
    P[((size_t)(b * 31 + chunk)) * HID + 2 * t + 1] = s1;
}

__global__ void sum_h_red(const float* __restrict__ P, float* __restrict__ S1B) {
    int idx = blockIdx.x * 256 + threadIdx.x;
    if (idx >= HID * NB) return;
    int k = idx >> 3, b = idx & 7;
    float s = 0.f;
    #pragma unroll
    for (int c = 0; c < 31; c++) s += P[((size_t)(b * 31 + c)) * HID + k];
    S1B[b * HID + k] = s;
}

// ---------------- fp16 mma.sync GEMM, 64x128 CTA, ldmatrix -------------------
// MODE 0: A from AP; epilogue -> pack H1P.   MODE 1: A = local agg of H1P;
// epilogue -> atomicMax out.  Both add TT[b][n] (S-term) + bias before lrelu.
template<int K2TOT, int NTOT, int MODE>
__global__ __launch_bounds__(256)
void gemm_mma(const uint32_t* __restrict__ AP,
              const uint32_t* __restrict__ H1P,
              const uint32_t* __restrict__ BhP,
              const float* __restrict__ bias, const float* __restrict__ TT,
              void* __restrict__ OUTP) {
    extern __shared__ uint32_t smu[];
    constexpr int ROWW  = 20;
    constexpr int ATILE = 64 * ROWW;
    constexpr int BTILE = 128 * ROWW;
    constexpr int BUFW  = ATILE + BTILE;
    constexpr int NC    = K2TOT / 16;

    const int tid  = threadIdx.x;
    const int lane = tid & 31;
    const int wid  = tid >> 5;
    const int bm   = blockIdx.y * 64;
    const int bn   = blockIdx.x * 128;
    const int wm   = (wid & 1) * 32;
    const int wn   = (wid >> 1) * 32;
    const int g    = lane >> 2, tg = lane & 3;
    const uint32_t sb = smem_u32(smu);

    const int mat = lane >> 3, r8 = lane & 7;
    const int aoff0 = (wm + (mat & 1) * 8 + r8) * ROWW + (mat >> 1) * 4;
    const int aoff1 = aoff0 + 16 * ROWW;
    const int boff0 = ATILE + (wn + (mat >> 1) * 8 + r8) * ROWW + (mat & 1) * 4;
    const int boff1 = boff0 + 16 * ROWW;

    float acc[2][4][4];
    #pragma unroll
    for (int i = 0; i < 2; i++)
        #pragma unroll
        for (int j = 0; j < 4; j++)
            #pragma unroll
            for (int e = 0; e < 4; e++) acc[i][j][e] = 0.f;

    auto load_chunk = [&](int ch) {
        const int st   = ch & 1;
        const int k2_0 = ch * 16;
        const uint32_t bufb = sb + (uint32_t)(st * BUFW) * 4;
        #pragma unroll
        for (int i = 0; i < 2; i++) {
            int q   = tid + i * 256;
            int row = q >> 2, seg = q & 3;
            const uint32_t* src = BhP + (size_t)(bn + row) * K2TOT + k2_0 + seg * 4;
            uint32_t dst = bufb + (uint32_t)(ATILE + row * ROWW + seg * 4) * 4;
            CP_ASYNC16(dst, src);
        }
        if (MODE == 0) {
            int row = tid >> 2, seg = tid & 3;
            const uint32_t* src = AP + (size_t)(bm + row) * K2TOT + k2_0 + seg * 4;
            uint32_t dst = bufb + (uint32_t)(row * ROWW + seg * 4) * 4;
            CP_ASYNC16(dst, src);
        } else {
            uint32_t* bA = smu + st * BUFW;
            int mi = tid >> 2, seg = tid & 3;
            int m = bm + mi;
            int b = m / HW; if (b > NB - 1) b = NB - 1;
            float db = dinv_of(b);
            float c0 = db * db;
            bool hasm = (b > 0), hasp = (b < NB - 1);
            float cm = hasm ? db * dinv_of(b - 1) : 0.f;
            float cp = hasp ? db * dinv_of(b + 1) : 0.f;
            const uint32_t* hr = H1P + (size_t)m * K2TOT + k2_0 + seg * 4;
            uint4 h  = *(const uint4*)hr;
            uint4 hm = hasm ? *(const uint4*)(hr - (size_t)HW * K2TOT) : make_uint4(0,0,0,0);
            uint4 hp = hasp ? *(const uint4*)(hr + (size_t)HW * K2TOT) : make_uint4(0,0,0,0);
            const uint32_t* hw  = (const uint32_t*)&h;
            const uint32_t* hmw = (const uint32_t*)&hm;
            const uint32_t* hpw = (const uint32_t*)&hp;
            #pragma unroll
            for (int j = 0; j < 4; j++) {
                float2 f  = __half22float2(*(__half2*)&hw[j]);
                float2 fm = __half22float2(*(__half2*)&hmw[j]);
                float2 fp = __half22float2(*(__half2*)&hpw[j]);
                float v0 = c0 * f.x + cm * fm.x + cp * fp.x;
                float v1 = c0 * f.y + cm * fm.y + cp * fp.y;
                bA[mi * ROWW + seg * 4 + j] = f16x2_pack(v0, v1);
            }
        }
    };

    load_chunk(0);
    CP_COMMIT();

    for (int ch = 0; ch < NC; ch++) {
        if (ch + 1 < NC) load_chunk(ch + 1);
        CP_COMMIT();
        CP_WAIT1();
        __syncthreads();

        const uint32_t stb = sb + (uint32_t)((ch & 1) * BUFW) * 4;

        #pragma unroll
        for (int kk = 0; kk < 2; kk++) {
            const uint32_t kof = (uint32_t)(kk * 8) * 4;
            uint32_t a0[4], a1[4], b0[4], b1[4];
            LDSM_X4(a0[0], a0[1], a0[2], a0[3], stb + (uint32_t)aoff0 * 4 + kof);
            LDSM_X4(a1[0], a1[1], a1[2], a1[3], stb + (uint32_t)aoff1 * 4 + kof);
            LDSM_X4(b0[0], b0[1], b0[2], b0[3], stb + (uint32_t)boff0 * 4 + kof);
            LDSM_X4(b1[0], b1[1], b1[2], b1[3], stb + (uint32_t)boff1 * 4 + kof);
            MMA_F16(acc[0][0], a0[0], a0[1], a0[2], a0[3], b0[0], b0[1]);
            MMA_F16(acc[0][1], a0[0], a0[1], a0[2], a0[3], b0[2], b0[3]);
            MMA_F16(acc[0][2], a0[0], a0[1], a0[2], a0[3], b1[0], b1[1]);
            MMA_F16(acc[0][3], a0[0], a0[1], a0[2], a0[3], b1[2], b1[3]);
            MMA_F16(acc[1][0], a1[0], a1[1], a1[2], a1[3], b0[0], b0[1]);
            MMA_F16(acc[1][1], a1[0], a1[1], a1[2], a1[3], b0[2], b0[3]);
            MMA_F16(acc[1][2], a1[0], a1[1], a1[2], a1[3], b1[0], b1[1]);
            MMA_F16(acc[1][3], a1[0], a1[1], a1[2], a1[3], b1[2], b1[3]);
        }
        __syncthreads();
    }

    // epilogue: + S-term T[b][n] + bias, lrelu, then pack/atomicMax
    #pragma unroll
    for (int mt = 0; mt < 2; mt++) {
        int m0 = bm + wm + mt * 16 + g;
        bool v0 = m0 < Mrows, v8 = (m0 + 8) < Mrows;
        int b0i = m0 / HW;       if (b0i > NB - 1) b0i = NB - 1;
        int b8i = (m0 + 8) / HW; if (b8i > NB - 1) b8i = NB - 1;
        const float* tt0 = TT + b0i * NTOT;
        const float* tt8 = TT + b8i * NTOT;
        #pragma unroll
        for (int nt = 0; nt < 4; nt++) {
            int n = bn + wn + nt * 8 + 2 * tg;
            float bb0 = __ldg(&bias[n]), bb1 = __ldg(&bias[n + 1]);
            float c0 = acc[mt][nt][0] + bb0 + __ldg(&tt0[n]);
            float c1 = acc[mt][nt][1] + bb1 + __ldg(&tt0[n + 1]);
            float c2 = acc[mt][nt][2] + bb0 + __ldg(&tt8[n]);
            float c3 = acc[mt][nt][3] + bb1 + __ldg(&tt8[n + 1]);
            c0 = c0 > 0.f ? c0 : 0.01f * c0;
            c1 = c1 > 0.f ? c1 : 0.01f * c1;
            c2 = c2 > 0.f ? c2 : 0.01f * c2;
            c3 = c3 > 0.f ? c3 : 0.01f * c3;
            if (MODE == 0) {
                uint32_t* H = (uint32_t*)OUTP;
                int n2 = n >> 1;
                if (v0) H[(size_t)m0 * (NTOT / 2) + n2]       = f16x2_pack(c0, c1);
                if (v8) H[(size_t)(m0 + 8) * (NTOT / 2) + n2] = f16x2_pack(c2, c3);
            } else {
                float* out = (float*)OUTP;
                if (v0) {
                    int p = m0 - b0i * HW;
                    atomicMaxF(out + (size_t)n * HW + p, c0);
                    atomicMaxF(out + (size_t)(n + 1) * HW + p, c1);
                }
                if (v8) {
                    int p = m0 + 8 - b8i * HW;
                    atomicMaxF(out + (size_t)n * HW + p, c2);
                    atomicMaxF(out + (size_t)(n + 1) * HW + p, c3);
                }
            }
        }
    }
}

// ---------------- launcher ----------------------------------------------------
extern "C" void kernel_launch(void* const* d_in, const int* in_sizes, int n_in,
                              void* d_out, int out_size) {
    const float* x  = (const float*)d_in[0];
    const float* W1 = (const float*)d_in[1];
    const float* b1 = (const float*)d_in[2];
    const float* W2 = (const float*)d_in[3];
    const float* b2 = (const float*)d_in[4];
    float* out = (float*)d_out;

    float *S0, *P, *S1B, *T1, *T2;
    uint32_t *YP, *W1h, *W2h, *H1P;
    cudaGetSymbolAddress((void**)&S0,  g_S0);
    cudaGetSymbolAddress((void**)&YP,  g_YP);
    cudaGetSymbolAddress((void**)&W1h, g_W1hP);
    cudaGetSymbolAddress((void**)&W2h, g_W2hP);
    cudaGetSymbolAddress((void**)&H1P, g_H1P);
    cudaGetSymbolAddress((void**)&P,   g_P);
    cudaGetSymbolAddress((void**)&S1B, g_S1B);
    cudaGetSymbolAddress((void**)&T1,  g_T1);
    cudaGetSymbolAddress((void**)&T2,  g_T2);

    constexpr int SMEM = 2 * 3840 * 4;
    cudaFuncSetAttribute(gemm_mma<Cc / 2,  HID,  0>,
                         cudaFuncAttributeMaxDynamicSharedMemorySize, SMEM);
    cudaFuncSetAttribute(gemm_mma<HID / 2, OUTF, 1>,
                         cudaFuncAttributeMaxDynamicSharedMemorySize, SMEM);

    // 1) one fused prep launch: local agg -> YP, sums -> S0, W packs, out=-inf
    prep_fused<<<PREP_BLOCKS, 256>>>(x, W1, W2, S0, YP, W1h, W2h, out);

    // 2) S-term for layer 1: T1[b][n] (fp32, exact)
    t_small<Cc><<<HID, 256>>>(S0, W1, T1, HID);

    // 3) GEMM1: H1P = pack(lrelu(local@W1^T + T1 + b1))
    gemm_mma<Cc / 2, HID, 0><<<dim3(HID / 128, MP / 64), 256, SMEM>>>(
        YP, nullptr, W1h, b1, T1, H1P);

    // 4) per-sample sums of H1 (2-stage, deterministic, 8x31 grid)
    sum_h_part<<<dim3(NB, 31), 256>>>(H1P, P);
    sum_h_red<<<(HID * NB + 255) / 256, 256>>>(P, S1B);

    // 5) S-term for layer 2: T2[b][n]
    t_small<HID><<<OUTF, 256>>>(S1B, W2, T2, OUTF);

    // 6) GEMM2: out = max_b lrelu(local(H1)@W2^T + T2 + b2)  (fused agg + max)
    gemm_mma<HID / 2, OUTF, 1><<<dim3(OUTF / 128, MP / 64), 256, SMEM>>>(
        nullptr, H1P, W2h, b2, T2, out);
}

// round 15
// speedup vs baseline: 1.0239x; 1.0239x over previous
#include <cuda_runtime.h>
#include <cuda_fp16.h>
#include <math.h>
#include <cstdint>

// ---------------- problem constants ----------------------------------------
#define NB    8
#define Cc    256
#define HW    961
#define Mrows 7688
#define MP    7808          // padded M = 61*128
#define HID   512
#define OUTF  256
#define NMB   122           // m-blocks of 64 in GEMM1 grid

// ---------------- scratch (device globals; zero-initialized) ----------------
__device__ float    g_S0  [NB * Cc];
__device__ uint32_t g_YP  [MP * (Cc / 2)];     // LOCAL agg, packed fp16x2 [m][k2]
__device__ uint32_t g_W1hP[HID * (Cc / 2)];
__device__ uint32_t g_W2hP[OUTF * (HID / 2)];
__device__ uint32_t g_H1P [MP * (HID / 2)];    // H1 packed fp16x2 [m][k2]
__device__ float    g_P1  [NMB * 2 * HID];     // per-mblock per-sample-slot column sums
__device__ float    g_S1B [NB * HID];          // per-sample sums [b][k]
__device__ float    g_T1  [NB * HID];          // S-term epilogue corrections
__device__ float    g_T2  [NB * OUTF];

// ---------------- helpers ----------------------------------------------------
__device__ __forceinline__ uint32_t smem_u32(const void* p) {
    uint32_t a;
    asm("{ .reg .u64 t; cvta.to.shared.u64 t, %1; cvt.u32.u64 %0, t; }"
        : "=r"(a) : "l"(p));
    return a;
}

__device__ __forceinline__ float dinv_of(int b) {
    int deg = (b == 0 || b == NB - 1) ? 963 : 964;
    return 1.0f / sqrtf((float)deg);
}

__device__ __forceinline__ uint32_t f16x2_pack(float v0, float v1) {
    __half2 h = __floats2half2_rn(v0, v1);
    return *(uint32_t*)&h;
}

// deterministic float atomic max (dst inited to -inf)
__device__ __forceinline__ void atomicMaxF(float* addr, float v) {
    if (v >= 0.f) atomicMax((int*)addr, __float_as_int(v));
    else          atomicMin((unsigned int*)addr, (unsigned int)__float_as_int(v));
}

#define MMA_F16(d, a0, a1, a2, a3, b0, b1) \
    asm volatile("mma.sync.aligned.m16n8k16.row.col.f32.f16.f16.f32 " \
                 "{%0,%1,%2,%3},{%4,%5,%6,%7},{%8,%9},{%0,%1,%2,%3};" \
                 : "+f"((d)[0]), "+f"((d)[1]), "+f"((d)[2]), "+f"((d)[3]) \
                 : "r"(a0), "r"(a1), "r"(a2), "r"(a3), "r"(b0), "r"(b1))

#define LDSM_X4(r0, r1, r2, r3, addr) \
    asm volatile("ldmatrix.sync.aligned.m8n8.x4.shared.b16 {%0,%1,%2,%3}, [%4];" \
                 : "=r"(r0), "=r"(r1), "=r"(r2), "=r"(r3) : "r"(addr))

#define CP_ASYNC16(dst32, src) \
    asm volatile("cp.async.cg.shared.global [%0], [%1], 16;" :: "r"(dst32), "l"(src))
#define CP_COMMIT()  asm volatile("cp.async.commit_group;" ::: "memory")
#define CP_WAIT1()   asm volatile("cp.async.wait_group 1;" ::: "memory")

// ---------------- fused prep kernel (one launch, 5 jobs) ----------------------
#define PREP_BLOCKS 3409
__global__ void prep_fused(const float* __restrict__ x,
                           const float* __restrict__ W1,
                           const float* __restrict__ W2,
                           float* __restrict__ S0,
                           uint32_t* __restrict__ YP,
                           uint32_t* __restrict__ W1h,
                           uint32_t* __restrict__ W2h,
                           float* __restrict__ out) {
    __shared__ float red[8];
    const int blk = blockIdx.x;
    const int tid = threadIdx.x;

    if (blk < 992) {
        int mblk = blk % 31, cq = blk / 31;
        int m = mblk * 256 + tid;
        if (m >= Mrows) return;
        int b = m / HW, p = m - b * HW;
        float db = dinv_of(b);
        float c0 = db * db;
        float cm = (b > 0)      ? db * dinv_of(b - 1) : 0.f;
        float cp = (b < NB - 1) ? db * dinv_of(b + 1) : 0.f;
        uint32_t w[4];
        #pragma unroll
        for (int j = 0; j < 4; j++) {
            float v2[2];
            #pragma unroll
            for (int e = 0; e < 2; e++) {
                int c = cq * 8 + j * 2 + e;
                size_t xi = (size_t)(b * Cc + c) * HW + p;
                float vv = c0 * __ldg(&x[xi]);
                if (b > 0)      vv += cm * __ldg(&x[xi - (size_t)Cc * HW]);
                if (b < NB - 1) vv += cp * __ldg(&x[xi + (size_t)Cc * HW]);
                v2[e] = vv;
            }
            w[j] = f16x2_pack(v2[0], v2[1]);
        }
        *(uint4*)(YP + (size_t)m * (Cc / 2) + cq * 4) = make_uint4(w[0], w[1], w[2], w[3]);
    } else if (blk < 3040) {
        int bc = blk - 992;
        const float* src = x + (size_t)bc * HW;
        float s = 0.f;
        for (int p = tid; p < HW; p += 256) s += src[p];
        #pragma unroll
        for (int off = 16; off; off >>= 1) s += __shfl_down_sync(0xffffffffu, s, off);
        if ((tid & 31) == 0) red[tid >> 5] = s;
        __syncthreads();
        if (tid < 8) {
            s = red[tid];
            #pragma unroll
            for (int off = 4; off; off >>= 1) s += __shfl_down_sync(0xffu, s, off);
            if (tid == 0) S0[bc] = s;
        }
    } else if (blk < 3168) {
        bool isW1 = blk < 3104;
        const float* W = isW1 ? W1 : W2;
        uint32_t* Wh = isW1 ? W1h : W2h;
        int base = ((blk - (isW1 ? 3040 : 3104)) * 256 + tid) * 4;
        float4 a = ((const float4*)W)[base / 2];
        float4 c = ((const float4*)W)[base / 2 + 1];
        Wh[base]     = f16x2_pack(a.x, a.y);
        Wh[base + 1] = f16x2_pack(a.z, a.w);
        Wh[base + 2] = f16x2_pack(c.x, c.y);
        Wh[base + 3] = f16x2_pack(c.z, c.w);
    } else {
        int i4 = (blk - 3168) * 256 + tid;
        if (i4 < OUTF * HW / 4) {
            float ninf = __int_as_float(0xFF800000);
            ((float4*)out)[i4] = make_float4(ninf, ninf, ninf, ninf);
        }
    }
}

// ---------------- tiny S-term GEMM: T[b][n] = c0_b * sum_k S[b,k] W[n,k] -----
template<int K>
__global__ void t_small(const float* __restrict__ S, const float* __restrict__ W,
                        float* __restrict__ T, int N) {
    int w = threadIdx.x >> 5, lane = threadIdx.x & 31;
    int idx = blockIdx.x * 8 + w;
    if (idx >= N * NB) return;
    int n = idx >> 3, b = idx & 7;
    float s = 0.f;
    for (int k = lane; k < K; k += 32)
        s += __ldg(&S[b * K + k]) * __ldg(&W[n * K + k]);
    #pragma unroll
    for (int off = 16; off; off >>= 1) s += __shfl_down_sync(0xffffffffu, s, off);
    if (lane == 0) {
        float db = dinv_of(b);
        T[b * N + n] = db * db * s;
    }
}

// ---------------- fold P1 partials -> S1B[b][k] -------------------------------
__global__ void sum_h_red(const float* __restrict__ P1, float* __restrict__ S1B) {
    int idx = blockIdx.x * 256 + threadIdx.x;
    if (idx >= HID * NB) return;
    int k = idx >> 3, b = idx & 7;
    int mb0 = (b * HW) / 64;
    int mb1 = ((b + 1) * HW - 1) / 64;
    if (mb1 > NMB - 1) mb1 = NMB - 1;
    float s = 0.f;
    for (int mb = mb0; mb <= mb1; mb++) {
        int bl = (mb * 64) / HW;
        int sidx = b - bl;                 // 0 or 1
        s += __ldg(&P1[((size_t)mb * 2 + sidx) * HID + k]);
    }
    S1B[b * HID + k] = s;
}

// ---------------- fp16 mma.sync GEMM, 64x128 CTA, ldmatrix -------------------
// MODE 0: A from AP; epilogue -> pack H1P + per-CTA column-sum partials P1.
// MODE 1: A = local agg of H1P; epilogue -> atomicMax out.
// Both add TT[b][n] (S-term) + bias before lrelu.
template<int K2TOT, int NTOT, int MODE>
__global__ __launch_bounds__(256)
void gemm_mma(const uint32_t* __restrict__ AP,
              const uint32_t* __restrict__ H1P,
              const uint32_t* __restrict__ BhP,
              const float* __restrict__ bias, const float* __restrict__ TT,
              float* __restrict__ P1, void* __restrict__ OUTP) {
    extern __shared__ uint32_t smu[];
    constexpr int ROWW  = 20;
    constexpr int ATILE = 64 * ROWW;
    constexpr int BTILE = 128 * ROWW;
    constexpr int BUFW  = ATILE + BTILE;
    constexpr int NC    = K2TOT / 16;

    const int tid  = threadIdx.x;
    const int lane = tid & 31;
    const int wid  = tid >> 5;
    const int bm   = blockIdx.y * 64;
    const int bn   = blockIdx.x * 128;
    const int wm   = (wid & 1) * 32;
    const int wn   = (wid >> 1) * 32;
    const int g    = lane >> 2, tg = lane & 3;
    const uint32_t sb = smem_u32(smu);

    const int mat = lane >> 3, r8 = lane & 7;
    const int aoff0 = (wm + (mat & 1) * 8 + r8) * ROWW + (mat >> 1) * 4;
    const int aoff1 = aoff0 + 16 * ROWW;
    const int boff0 = ATILE + (wn + (mat >> 1) * 8 + r8) * ROWW + (mat & 1) * 4;
    const int boff1 = boff0 + 16 * ROWW;

    float acc[2][4][4];
    #pragma unroll
    for (int i = 0; i < 2; i++)
        #pragma unroll
        for (int j = 0; j < 4; j++)
            #pragma unroll
            for (int e = 0; e < 4; e++) acc[i][j][e] = 0.f;

    auto load_chunk = [&](int ch) {
        const int st   = ch & 1;
        const int k2_0 = ch * 16;
        const uint32_t bufb = sb + (uint32_t)(st * BUFW) * 4;
        #pragma unroll
        for (int i = 0; i < 2; i++) {
            int q   = tid + i * 256;
            int row = q >> 2, seg = q & 3;
            const uint32_t* src = BhP + (size_t)(bn + row) * K2TOT + k2_0 + seg * 4;
            uint32_t dst = bufb + (uint32_t)(ATILE + row * ROWW + seg * 4) * 4;
            CP_ASYNC16(dst, src);
        }
        if (MODE == 0) {
            int row = tid >> 2, seg = tid & 3;
            const uint32_t* src = AP + (size_t)(bm + row) * K2TOT + k2_0 + seg * 4;
            uint32_t dst = bufb + (uint32_t)(row * ROWW + seg * 4) * 4;
            CP_ASYNC16(dst, src);
        } else {
            uint32_t* bA = smu + st * BUFW;
            int mi = tid >> 2, seg = tid & 3;
            int m = bm + mi;
            int b = m / HW; if (b > NB - 1) b = NB - 1;
            float db = dinv_of(b);
            float c0 = db * db;
            bool hasm = (b > 0), hasp = (b < NB - 1);
            float cm = hasm ? db * dinv_of(b - 1) : 0.f;
            float cp = hasp ? db * dinv_of(b + 1) : 0.f;
            const uint32_t* hr = H1P + (size_t)m * K2TOT + k2_0 + seg * 4;
            uint4 h  = *(const uint4*)hr;
            uint4 hm = hasm ? *(const uint4*)(hr - (size_t)HW * K2TOT) : make_uint4(0,0,0,0);
            uint4 hp = hasp ? *(const uint4*)(hr + (size_t)HW * K2TOT) : make_uint4(0,0,0,0);
            const uint32_t* hw  = (const uint32_t*)&h;
            const uint32_t* hmw = (const uint32_t*)&hm;
            const uint32_t* hpw = (const uint32_t*)&hp;
            #pragma unroll
            for (int j = 0; j < 4; j++) {
                float2 f  = __half22float2(*(__half2*)&hw[j]);
                float2 fm = __half22float2(*(__half2*)&hmw[j]);
                float2 fp = __half22float2(*(__half2*)&hpw[j]);
                float v0 = c0 * f.x + cm * fm.x + cp * fp.x;
                float v1 = c0 * f.y + cm * fm.y + cp * fp.y;
                bA[mi * ROWW + seg * 4 + j] = f16x2_pack(v0, v1);
            }
        }
    };

    load_chunk(0);
    CP_COMMIT();

    for (int ch = 0; ch < NC; ch++) {
        if (ch + 1 < NC) load_chunk(ch + 1);
        CP_COMMIT();
        CP_WAIT1();
        __syncthreads();

        const uint32_t stb = sb + (uint32_t)((ch & 1) * BUFW) * 4;

        #pragma unroll
        for (int kk = 0; kk < 2; kk++) {
            const uint32_t kof = (uint32_t)(kk * 8) * 4;
            uint32_t a0[4], a1[4], b0[4], b1[4];
            LDSM_X4(a0[0], a0[1], a0[2], a0[3], stb + (uint32_t)aoff0 * 4 + kof);
            LDSM_X4(a1[0], a1[1], a1[2], a1[3], stb + (uint32_t)aoff1 * 4 + kof);
            LDSM_X4(b0[0], b0[1], b0[2], b0[3], stb + (uint32_t)boff0 * 4 + kof);
            LDSM_X4(b1[0], b1[1], b1[2], b1[3], stb + (uint32_t)boff1 * 4 + kof);
            MMA_F16(acc[0][0], a0[0], a0[1], a0[2], a0[3], b0[0], b0[1]);
            MMA_F16(acc[0][1], a0[0], a0[1], a0[2], a0[3], b0[2], b0[3]);
            MMA_F16(acc[0][2], a0[0], a0[1], a0[2], a0[3], b1[0], b1[1]);
            MMA_F16(acc[0][3], a0[0], a0[1], a0[2], a0[3], b1[2], b1[3]);
            MMA_F16(acc[1][0], a1[0], a1[1], a1[2], a1[3], b0[0], b0[1]);
            MMA_F16(acc[1][1], a1[0], a1[1], a1[2], a1[3], b0[2], b0[3]);
            MMA_F16(acc[1][2], a1[0], a1[1], a1[2], a1[3], b1[0], b1[1]);
            MMA_F16(acc[1][3], a1[0], a1[1], a1[2], a1[3], b1[2], b1[3]);
        }
        __syncthreads();
    }

    // ---------------- epilogue -----------------------------------------------
    const int b_lo_raw = bm / HW;
    const int b_lo = (b_lo_raw > NB - 1) ? NB - 1 : b_lo_raw;
    float sumS[2][8];
    #pragma unroll
    for (int s = 0; s < 2; s++)
        #pragma unroll
        for (int i = 0; i < 8; i++) sumS[s][i] = 0.f;

    #pragma unroll
    for (int mt = 0; mt < 2; mt++) {
        int m0 = bm + wm + mt * 16 + g;
        bool v0 = m0 < Mrows, v8 = (m0 + 8) < Mrows;
        int b0i = m0 / HW;       if (b0i > NB - 1) b0i = NB - 1;
        int b8i = (m0 + 8) / HW; if (b8i > NB - 1) b8i = NB - 1;
        const float* tt0 = TT + b0i * NTOT;
        const float* tt8 = TT + b8i * NTOT;
        int s0 = b0i - b_lo; if (s0 > 1) s0 = 1; if (s0 < 0) s0 = 0;
        int s8 = b8i - b_lo; if (s8 > 1) s8 = 1; if (s8 < 0) s8 = 0;
        #pragma unroll
        for (int nt = 0; nt < 4; nt++) {
            int n = bn + wn + nt * 8 + 2 * tg;
            float bb0 = __ldg(&bias[n]), bb1 = __ldg(&bias[n + 1]);
            float c0 = acc[mt][nt][0] + bb0 + __ldg(&tt0[n]);
            float c1 = acc[mt][nt][1] + bb1 + __ldg(&tt0[n + 1]);
            float c2 = acc[mt][nt][2] + bb0 + __ldg(&tt8[n]);
            float c3 = acc[mt][nt][3] + bb1 + __ldg(&tt8[n + 1]);
            c0 = c0 > 0.f ? c0 : 0.01f * c0;
            c1 = c1 > 0.f ? c1 : 0.01f * c1;
            c2 = c2 > 0.f ? c2 : 0.01f * c2;
            c3 = c3 > 0.f ? c3 : 0.01f * c3;
            if (MODE == 0) {
                uint32_t* H = (uint32_t*)OUTP;
                int n2 = n >> 1;
                if (v0) {
                    H[(size_t)m0 * (NTOT / 2) + n2] = f16x2_pack(c0, c1);
                    sumS[s0][nt * 2]     += c0;
                    sumS[s0][nt * 2 + 1] += c1;
                }
                if (v8) {
                    H[(size_t)(m0 + 8) * (NTOT / 2) + n2] = f16x2_pack(c2, c3);
                    sumS[s8][nt * 2]     += c2;
                    sumS[s8][nt * 2 + 1] += c3;
                }
            } else {
                float* out = (float*)OUTP;
                if (v0) {
                    int p = m0 - b0i * HW;
                    atomicMaxF(out + (size_t)n * HW + p, c0);
                    atomicMaxF(out + (size_t)(n + 1) * HW + p, c1);
                }
                if (v8) {
                    int p = m0 + 8 - b8i * HW;
                    atomicMaxF(out + (size_t)n * HW + p, c2);
                    atomicMaxF(out + (size_t)(n + 1) * HW + p, c3);
                }
            }
        }
    }

    if (MODE == 0) {
        // reduce sumS over the 8 g-lanes (stride-4 lanes share tg / n-columns)
        #pragma unroll
        for (int off = 16; off >= 4; off >>= 1)
            #pragma unroll
            for (int s = 0; s < 2; s++)
                #pragma unroll
                for (int i = 0; i < 8; i++)
                    sumS[s][i] += __shfl_down_sync(0xffffffffu, sumS[s][i], off);
        float* sred = (float*)smu;            // [8 warps][2 slots][32 n]
        __syncthreads();                      // mainloop smem fully consumed
        if (lane < 4) {
            #pragma unroll
            for (int s = 0; s < 2; s++)
                #pragma unroll
                for (int i = 0; i < 8; i++) {
                    int nl = (i >> 1) * 8 + 2 * lane + (i & 1);
                    sred[(wid * 2 + s) * 32 + nl] = sumS[s][i];
                }
        }
        __syncthreads();
        {
            int s  = tid >> 7;                // 0..1
            int nl = tid & 127;               // 0..127
            int wp = nl >> 5;                 // warp pair 0..3
            float v = sred[((wp * 2 + 0) * 2 + s) * 32 + (nl & 31)]
                    + sred[((wp * 2 + 1) * 2 + s) * 32 + (nl & 31)];
            P1[((size_t)blockIdx.y * 2 + s) * NTOT + bn + nl] = v;
        }
    }
}

// ---------------- launcher ----------------------------------------------------
extern "C" void kernel_launch(void* const* d_in, const int* in_sizes, int n_in,
                              void* d_out, int out_size) {
    const float* x  = (const float*)d_in[0];
    const float* W1 = (const float*)d_in[1];
    const float* b1 = (const float*)d_in[2];
    const float* W2 = (const float*)d_in[3];
    const float* b2 = (const float*)d_in[4];
    float* out = (float*)d_out;

    float *S0, *P1, *S1B, *T1, *T2;
    uint32_t *YP, *W1h, *W2h, *H1P;
    cudaGetSymbolAddress((void**)&S0,  g_S0);
    cudaGetSymbolAddress((void**)&YP,  g_YP);
    cudaGetSymbolAddress((void**)&W1h, g_W1hP);
    cudaGetSymbolAddress((void**)&W2h, g_W2hP);
    cudaGetSymbolAddress((void**)&H1P, g_H1P);
    cudaGetSymbolAddress((void**)&P1,  g_P1);
    cudaGetSymbolAddress((void**)&S1B, g_S1B);
    cudaGetSymbolAddress((void**)&T1,  g_T1);
    cudaGetSymbolAddress((void**)&T2,  g_T2);

    constexpr int SMEM = 2 * 3840 * 4;
    cudaFuncSetAttribute(gemm_mma<Cc / 2,  HID,  0>,
                         cudaFuncAttributeMaxDynamicSharedMemorySize, SMEM);
    cudaFuncSetAttribute(gemm_mma<HID / 2, OUTF, 1>,
                         cudaFuncAttributeMaxDynamicSharedMemorySize, SMEM);

    // 1) fused prep: local agg -> YP, sums -> S0, W packs, out = -inf
    prep_fused<<<PREP_BLOCKS, 256>>>(x, W1, W2, S0, YP, W1h, W2h, out);

    // 2) S-term for layer 1: T1[b][n] (fp32, exact)
    t_small<Cc><<<HID, 256>>>(S0, W1, T1, HID);

    // 3) GEMM1: H1P = pack(lrelu(local@W1^T + T1 + b1)); P1 column-sum partials
    gemm_mma<Cc / 2, HID, 0><<<dim3(HID / 128, NMB), 256, SMEM>>>(
        YP, nullptr, W1h, b1, T1, P1, H1P);

    // 4) fold partials -> S1B (deterministic)
    sum_h_red<<<(HID * NB + 255) / 256, 256>>>(P1, S1B);

    // 5) S-term for layer 2: T2[b][n]
    t_small<HID><<<OUTF, 256>>>(S1B, W2, T2, OUTF);

    // 6) GEMM2: out = max_b lrelu(local(H1)@W2^T + T2 + b2) (fused agg + max)
    gemm_mma<HID / 2, OUTF, 1><<<dim3(OUTF / 128, NMB), 256, SMEM>>>(
        nullptr, H1P, W2h, b2, T2, nullptr, out);
}

// round 16
// speedup vs baseline: 1.0931x; 1.0676x over previous
#include <cuda_runtime.h>
#include <cuda_fp16.h>
#include <math.h>
#include <cstdint>

// ---------------- problem constants ----------------------------------------
#define NB    8
#define Cc    256
#define HW    961
#define Mrows 7688
#define MP    7808          // padded M = 61*128
#define HID   512
#define OUTF  256
#define NMB   122           // m-blocks of 64 in GEMM1 grid

// ---------------- scratch (device globals; zero-initialized) ----------------
__device__ float    g_S0  [NB * Cc];
__device__ uint32_t g_YP  [MP * (Cc / 2)];     // LOCAL agg, packed fp16x2 [m][k2]
__device__ uint32_t g_W1hP[HID * (Cc / 2)];
__device__ uint32_t g_W2hP[OUTF * (HID / 2)];
__device__ uint32_t g_H1P [MP * (HID / 2)];    // H1 packed fp16x2 [m][k2]
__device__ float    g_P1  [NMB * 2 * HID];     // per-mblock per-sample-slot column sums
__device__ float    g_S1B [NB * HID];          // per-sample sums [b][k]
__device__ float    g_T1  [NB * HID];          // S-term epilogue corrections
__device__ float    g_T2  [NB * OUTF];

// ---------------- helpers ----------------------------------------------------
__device__ __forceinline__ uint32_t smem_u32(const void* p) {
    uint32_t a;
    asm("{ .reg .u64 t; cvta.to.shared.u64 t, %1; cvt.u32.u64 %0, t; }"
        : "=r"(a) : "l"(p));
    return a;
}

__device__ __forceinline__ float dinv_of(int b) {
    int deg = (b == 0 || b == NB - 1) ? 963 : 964;
    return 1.0f / sqrtf((float)deg);
}

__device__ __forceinline__ uint32_t f16x2_pack(float v0, float v1) {
    __half2 h = __floats2half2_rn(v0, v1);
    return *(uint32_t*)&h;
}

// deterministic float atomic max (dst inited to -inf)
__device__ __forceinline__ void atomicMaxF(float* addr, float v) {
    if (v >= 0.f) atomicMax((int*)addr, __float_as_int(v));
    else          atomicMin((unsigned int*)addr, (unsigned int)__float_as_int(v));
}

#define MMA_F16(d, a0, a1, a2, a3, b0, b1) \
    asm volatile("mma.sync.aligned.m16n8k16.row.col.f32.f16.f16.f32 " \
                 "{%0,%1,%2,%3},{%4,%5,%6,%7},{%8,%9},{%0,%1,%2,%3};" \
                 : "+f"((d)[0]), "+f"((d)[1]), "+f"((d)[2]), "+f"((d)[3]) \
                 : "r"(a0), "r"(a1), "r"(a2), "r"(a3), "r"(b0), "r"(b1))

#define LDSM_X4(r0, r1, r2, r3, addr) \
    asm volatile("ldmatrix.sync.aligned.m8n8.x4.shared.b16 {%0,%1,%2,%3}, [%4];" \
                 : "=r"(r0), "=r"(r1), "=r"(r2), "=r"(r3) : "r"(addr))

#define CP_ASYNC16(dst32, src) \
    asm volatile("cp.async.cg.shared.global [%0], [%1], 16;" :: "r"(dst32), "l"(src))
#define CP_COMMIT()  asm volatile("cp.async.commit_group;" ::: "memory")
#define CP_WAIT1()   asm volatile("cp.async.wait_group 1;" ::: "memory")

// ---------------- fused prep kernel (one launch, 5 jobs) ----------------------
#define PREP_BLOCKS 3409
__global__ void prep_fused(const float* __restrict__ x,
                           const float* __restrict__ W1,
                           const float* __restrict__ W2,
                           float* __restrict__ S0,
                           uint32_t* __restrict__ YP,
                           uint32_t* __restrict__ W1h,
                           uint32_t* __restrict__ W2h,
                           float* __restrict__ out) {
    __shared__ float red[8];
    const int blk = blockIdx.x;
    const int tid = threadIdx.x;

    if (blk < 992) {
        int mblk = blk % 31, cq = blk / 31;
        int m = mblk * 256 + tid;
        if (m >= Mrows) return;
        int b = m / HW, p = m - b * HW;
        float db = dinv_of(b);
        float c0 = db * db;
        float cm = (b > 0)      ? db * dinv_of(b - 1) : 0.f;
        float cp = (b < NB - 1) ? db * dinv_of(b + 1) : 0.f;
        uint32_t w[4];
        #pragma unroll
        for (int j = 0; j < 4; j++) {
            float v2[2];
            #pragma unroll
            for (int e = 0; e < 2; e++) {
                int c = cq * 8 + j * 2 + e;
                size_t xi = (size_t)(b * Cc + c) * HW + p;
                float vv = c0 * __ldg(&x[xi]);
                if (b > 0)      vv += cm * __ldg(&x[xi - (size_t)Cc * HW]);
                if (b < NB - 1) vv += cp * __ldg(&x[xi + (size_t)Cc * HW]);
                v2[e] = vv;
            }
            w[j] = f16x2_pack(v2[0], v2[1]);
        }
        *(uint4*)(YP + (size_t)m * (Cc / 2) + cq * 4) = make_uint4(w[0], w[1], w[2], w[3]);
    } else if (blk < 3040) {
        int bc = blk - 992;
        const float* src = x + (size_t)bc * HW;
        float s = 0.f;
        for (int p = tid; p < HW; p += 256) s += src[p];
        #pragma unroll
        for (int off = 16; off; off >>= 1) s += __shfl_down_sync(0xffffffffu, s, off);
        if ((tid & 31) == 0) red[tid >> 5] = s;
        __syncthreads();
        if (tid < 8) {
            s = red[tid];
            #pragma unroll
            for (int off = 4; off; off >>= 1) s += __shfl_down_sync(0xffu, s, off);
            if (tid == 0) S0[bc] = s;
        }
    } else if (blk < 3168) {
        bool isW1 = blk < 3104;
        const float* W = isW1 ? W1 : W2;
        uint32_t* Wh = isW1 ? W1h : W2h;
        int base = ((blk - (isW1 ? 3040 : 3104)) * 256 + tid) * 4;
        float4 a = ((const float4*)W)[base / 2];
        float4 c = ((const float4*)W)[base / 2 + 1];
        Wh[base]     = f16x2_pack(a.x, a.y);
        Wh[base + 1] = f16x2_pack(a.z, a.w);
        Wh[base + 2] = f16x2_pack(c.x, c.y);
        Wh[base + 3] = f16x2_pack(c.z, c.w);
    } else {
        int i4 = (blk - 3168) * 256 + tid;
        if (i4 < OUTF * HW / 4) {
            float ninf = __int_as_float(0xFF800000);
            ((float4*)out)[i4] = make_float4(ninf, ninf, ninf, ninf);
        }
    }
}

// ---------------- tiny S-term GEMM: T[b][n] = c0_b * sum_k S[b,k] W[n,k] -----
template<int K>
__global__ void t_small(const float* __restrict__ S, const float* __restrict__ W,
                        float* __restrict__ T, int N) {
    int w = threadIdx.x >> 5, lane = threadIdx.x & 31;
    int idx = blockIdx.x * 8 + w;
    if (idx >= N * NB) return;
    int n = idx >> 3, b = idx & 7;
    float s = 0.f;
    #pragma unroll
    for (int k = lane; k < K; k += 32)
        s += __ldg(&S[b * K + k]) * __ldg(&W[n * K + k]);
    #pragma unroll
    for (int off = 16; off; off >>= 1) s += __shfl_down_sync(0xffffffffu, s, off);
    if (lane == 0) {
        float db = dinv_of(b);
        T[b * N + n] = db * db * s;
    }
}

// ---------------- fold P1 partials -> S1B[b][k]  (fixed 17-deep, unrolled) ----
__global__ void sum_h_red(const float* __restrict__ P1, float* __restrict__ S1B) {
    int idx = blockIdx.x * 256 + threadIdx.x;
    if (idx >= HID * NB) return;
    int k = idx >> 3, b = idx & 7;
    int mb0 = (b * HW) / 64;
    int mb1 = ((b + 1) * HW - 1) / 64;
    if (mb1 > NMB - 1) mb1 = NMB - 1;
    float s = 0.f;
    #pragma unroll
    for (int i = 0; i < 17; i++) {
        int mb = mb0 + i;
        if (mb <= mb1) {
            int bl = (mb * 64) / HW;
            int sidx = b - bl;                 // 0 or 1
            s += __ldg(&P1[((size_t)mb * 2 + sidx) * HID + k]);
        }
    }
    S1B[b * HID + k] = s;
}

// ---------------- fp16 mma.sync GEMM, 64x128 CTA, ldmatrix -------------------
// MODE 0: A from AP; epilogue -> pack H1P + per-CTA column-sum partials P1.
// MODE 1: A = local agg of H1P; epilogue -> atomicMax out.
// Both add TT[b][n] (S-term) + bias before lrelu.
template<int K2TOT, int NTOT, int MODE>
__global__ __launch_bounds__(256)
void gemm_mma(const uint32_t* __restrict__ AP,
              const uint32_t* __restrict__ H1P,
              const uint32_t* __restrict__ BhP,
              const float* __restrict__ bias, const float* __restrict__ TT,
              float* __restrict__ P1, void* __restrict__ OUTP) {
    extern __shared__ uint32_t smu[];
    constexpr int ROWW  = 20;
    constexpr int ATILE = 64 * ROWW;
    constexpr int BTILE = 128 * ROWW;
    constexpr int BUFW  = ATILE + BTILE;
    constexpr int NC    = K2TOT / 16;

    const int tid  = threadIdx.x;
    const int lane = tid & 31;
    const int wid  = tid >> 5;
    const int bm   = blockIdx.y * 64;
    const int bn   = blockIdx.x * 128;
    const int wm   = (wid & 1) * 32;
    const int wn   = (wid >> 1) * 32;
    const int g    = lane >> 2, tg = lane & 3;
    const uint32_t sb = smem_u32(smu);

    const int mat = lane >> 3, r8 = lane & 7;
    const int aoff0 = (wm + (mat & 1) * 8 + r8) * ROWW + (mat >> 1) * 4;
    const int aoff1 = aoff0 + 16 * ROWW;
    const int boff0 = ATILE + (wn + (mat >> 1) * 8 + r8) * ROWW + (mat & 1) * 4;
    const int boff1 = boff0 + 16 * ROWW;

    float acc[2][4][4];
    #pragma unroll
    for (int i = 0; i < 2; i++)
        #pragma unroll
        for (int j = 0; j < 4; j++)
            #pragma unroll
            for (int e = 0; e < 4; e++) acc[i][j][e] = 0.f;

    auto load_chunk = [&](int ch) {
        const int st   = ch & 1;
        const int k2_0 = ch * 16;
        const uint32_t bufb = sb + (uint32_t)(st * BUFW) * 4;
        #pragma unroll
        for (int i = 0; i < 2; i++) {
            int q   = tid + i * 256;
            int row = q >> 2, seg = q & 3;
            const uint32_t* src = BhP + (size_t)(bn + row) * K2TOT + k2_0 + seg * 4;
            uint32_t dst = bufb + (uint32_t)(ATILE + row * ROWW + seg * 4) * 4;
            CP_ASYNC16(dst, src);
        }
        if (MODE == 0) {
            int row = tid >> 2, seg = tid & 3;
            const uint32_t* src = AP + (size_t)(bm + row) * K2TOT + k2_0 + seg * 4;
            uint32_t dst = bufb + (uint32_t)(row * ROWW + seg * 4) * 4;
            CP_ASYNC16(dst, src);
        } else {
            uint32_t* bA = smu + st * BUFW;
            int mi = tid >> 2, seg = tid & 3;
            int m = bm + mi;
            int b = m / HW; if (b > NB - 1) b = NB - 1;
            float db = dinv_of(b);
            float c0 = db * db;
            bool hasm = (b > 0), hasp = (b < NB - 1);
            float cm = hasm ? db * dinv_of(b - 1) : 0.f;
            float cp = hasp ? db * dinv_of(b + 1) : 0.f;
            const uint32_t* hr = H1P + (size_t)m * K2TOT + k2_0 + seg * 4;
            uint4 h  = *(const uint4*)hr;
            uint4 hm = hasm ? *(const uint4*)(hr - (size_t)HW * K2TOT) : make_uint4(0,0,0,0);
            uint4 hp = hasp ? *(const uint4*)(hr + (size_t)HW * K2TOT) : make_uint4(0,0,0,0);
            const uint32_t* hw  = (const uint32_t*)&h;
            const uint32_t* hmw = (const uint32_t*)&hm;
            const uint32_t* hpw = (const uint32_t*)&hp;
            #pragma unroll
            for (int j = 0; j < 4; j++) {
                float2 f  = __half22float2(*(__half2*)&hw[j]);
                float2 fm = __half22float2(*(__half2*)&hmw[j]);
                float2 fp = __half22float2(*(__half2*)&hpw[j]);
                float v0 = c0 * f.x + cm * fm.x + cp * fp.x;
                float v1 = c0 * f.y + cm * fm.y + cp * fp.y;
                bA[mi * ROWW + seg * 4 + j] = f16x2_pack(v0, v1);
            }
        }
    };

    load_chunk(0);
    CP_COMMIT();

    for (int ch = 0; ch < NC; ch++) {
        if (ch + 1 < NC) load_chunk(ch + 1);
        CP_COMMIT();
        CP_WAIT1();
        __syncthreads();

        const uint32_t stb = sb + (uint32_t)((ch & 1) * BUFW) * 4;

        #pragma unroll
        for (int kk = 0; kk < 2; kk++) {
            const uint32_t kof = (uint32_t)(kk * 8) * 4;
            uint32_t a0[4], a1[4], b0[4], b1[4];
            LDSM_X4(a0[0], a0[1], a0[2], a0[3], stb + (uint32_t)aoff0 * 4 + kof);
            LDSM_X4(a1[0], a1[1], a1[2], a1[3], stb + (uint32_t)aoff1 * 4 + kof);
            LDSM_X4(b0[0], b0[1], b0[2], b0[3], stb + (uint32_t)boff0 * 4 + kof);
            LDSM_X4(b1[0], b1[1], b1[2], b1[3], stb + (uint32_t)boff1 * 4 + kof);
            MMA_F16(acc[0][0], a0[0], a0[1], a0[2], a0[3], b0[0], b0[1]);
            MMA_F16(acc[0][1], a0[0], a0[1], a0[2], a0[3], b0[2], b0[3]);
            MMA_F16(acc[0][2], a0[0], a0[1], a0[2], a0[3], b1[0], b1[1]);
            MMA_F16(acc[0][3], a0[0], a0[1], a0[2], a0[3], b1[2], b1[3]);
            MMA_F16(acc[1][0], a1[0], a1[1], a1[2], a1[3], b0[0], b0[1]);
            MMA_F16(acc[1][1], a1[0], a1[1], a1[2], a1[3], b0[2], b0[3]);
            MMA_F16(acc[1][2], a1[0], a1[1], a1[2], a1[3], b1[0], b1[1]);
            MMA_F16(acc[1][3], a1[0], a1[1], a1[2], a1[3], b1[2], b1[3]);
        }
        __syncthreads();
    }

    // ---------------- epilogue -----------------------------------------------
    const int b_lo_raw = bm / HW;
    const int b_lo = (b_lo_raw > NB - 1) ? NB - 1 : b_lo_raw;
    float sumS[2][8];
    #pragma unroll
    for (int s = 0; s < 2; s++)
        #pragma unroll
        for (int i = 0; i < 8; i++) sumS[s][i] = 0.f;

    #pragma unroll
    for (int mt = 0; mt < 2; mt++) {
        int m0 = bm + wm + mt * 16 + g;
        bool v0 = m0 < Mrows, v8 = (m0 + 8) < Mrows;
        int b0i = m0 / HW;       if (b0i > NB - 1) b0i = NB - 1;
        int b8i = (m0 + 8) / HW; if (b8i > NB - 1) b8i = NB - 1;
        const float* tt0 = TT + b0i * NTOT;
        const float* tt8 = TT + b8i * NTOT;
        int s0 = b0i - b_lo; if (s0 > 1) s0 = 1; if (s0 < 0) s0 = 0;
        int s8 = b8i - b_lo; if (s8 > 1) s8 = 1; if (s8 < 0) s8 = 0;
        #pragma unroll
        for (int nt = 0; nt < 4; nt++) {
            int n = bn + wn + nt * 8 + 2 * tg;
            float bb0 = __ldg(&bias[n]), bb1 = __ldg(&bias[n + 1]);
            float c0 = acc[mt][nt][0] + bb0 + __ldg(&tt0[n]);
            float c1 = acc[mt][nt][1] + bb1 + __ldg(&tt0[n + 1]);
            float c2 = acc[mt][nt][2] + bb0 + __ldg(&tt8[n]);
            float c3 = acc[mt][nt][3] + bb1 + __ldg(&tt8[n + 1]);
            c0 = c0 > 0.f ? c0 : 0.01f * c0;
            c1 = c1 > 0.f ? c1 : 0.01f * c1;
            c2 = c2 > 0.f ? c2 : 0.01f * c2;
            c3 = c3 > 0.f ? c3 : 0.01f * c3;
            if (MODE == 0) {
                uint32_t* H = (uint32_t*)OUTP;
                int n2 = n >> 1;
                if (v0) {
                    H[(size_t)m0 * (NTOT / 2) + n2] = f16x2_pack(c0, c1);
                    sumS[s0][nt * 2]     += c0;
                    sumS[s0][nt * 2 + 1] += c1;
                }
                if (v8) {
                    H[(size_t)(m0 + 8) * (NTOT / 2) + n2] = f16x2_pack(c2, c3);
                    sumS[s8][nt * 2]     += c2;
                    sumS[s8][nt * 2 + 1] += c3;
                }
            } else {
                float* out = (float*)OUTP;
                if (v0) {
                    int p = m0 - b0i * HW;
                    atomicMaxF(out + (size_t)n * HW + p, c0);
                    atomicMaxF(out + (size_t)(n + 1) * HW + p, c1);
                }
                if (v8) {
                    int p = m0 + 8 - b8i * HW;
                    atomicMaxF(out + (size_t)n * HW + p, c2);
                    atomicMaxF(out + (size_t)(n + 1) * HW + p, c3);
                }
            }
        }
    }

    if (MODE == 0) {
        #pragma unroll
        for (int off = 16; off >= 4; off >>= 1)
            #pragma unroll
            for (int s = 0; s < 2; s++)
                #pragma unroll
                for (int i = 0; i < 8; i++)
                    sumS[s][i] += __shfl_down_sync(0xffffffffu, sumS[s][i], off);
        float* sred = (float*)smu;
        __syncthreads();
        if (lane < 4) {
            #pragma unroll
            for (int s = 0; s < 2; s++)
                #pragma unroll
                for (int i = 0; i < 8; i++) {
                    int nl = (i >> 1) * 8 + 2 * lane + (i & 1);
                    sred[(wid * 2 + s) * 32 + nl] = sumS[s][i];
                }
        }
        __syncthreads();
        {
            int s  = tid >> 7;
            int nl = tid & 127;
            int wp = nl >> 5;
            float v = sred[((wp * 2 + 0) * 2 + s) * 32 + (nl & 31)]
                    + sred[((wp * 2 + 1) * 2 + s) * 32 + (nl & 31)];
            P1[((size_t)blockIdx.y * 2 + s) * NTOT + bn + nl] = v;
        }
    }
}

// ---------------- launcher ----------------------------------------------------
extern "C" void kernel_launch(void* const* d_in, const int* in_sizes, int n_in,
                              void* d_out, int out_size) {
    const float* x  = (const float*)d_in[0];
    const float* W1 = (const float*)d_in[1];
    const float* b1 = (const float*)d_in[2];
    const float* W2 = (const float*)d_in[3];
    const float* b2 = (const float*)d_in[4];
    float* out = (float*)d_out;

    float *S0, *P1, *S1B, *T1, *T2;
    uint32_t *YP, *W1h, *W2h, *H1P;
    cudaGetSymbolAddress((void**)&S0,  g_S0);
    cudaGetSymbolAddress((void**)&YP,  g_YP);
    cudaGetSymbolAddress((void**)&W1h, g_W1hP);
    cudaGetSymbolAddress((void**)&W2h, g_W2hP);
    cudaGetSymbolAddress((void**)&H1P, g_H1P);
    cudaGetSymbolAddress((void**)&P1,  g_P1);
    cudaGetSymbolAddress((void**)&S1B, g_S1B);
    cudaGetSymbolAddress((void**)&T1,  g_T1);
    cudaGetSymbolAddress((void**)&T2,  g_T2);

    constexpr int SMEM = 2 * 3840 * 4;
    cudaFuncSetAttribute(gemm_mma<Cc / 2,  HID,  0>,
                         cudaFuncAttributeMaxDynamicSharedMemorySize, SMEM);
    cudaFuncSetAttribute(gemm_mma<HID / 2, OUTF, 1>,
                         cudaFuncAttributeMaxDynamicSharedMemorySize, SMEM);

    // 1) fused prep: local agg -> YP, sums -> S0, W packs, out = -inf
    prep_fused<<<PREP_BLOCKS, 256>>>(x, W1, W2, S0, YP, W1h, W2h, out);

    // 2) S-term for layer 1: T1[b][n] (fp32, exact)
    t_small<Cc><<<HID, 256>>>(S0, W1, T1, HID);

    // 3) GEMM1: H1P = pack(lrelu(local@W1^T + T1 + b1)); P1 column-sum partials
    gemm_mma<Cc / 2, HID, 0><<<dim3(HID / 128, NMB), 256, SMEM>>>(
        YP, nullptr, W1h, b1, T1, P1, H1P);

    // 4) fold partials -> S1B (deterministic, unrolled 17-deep)
    sum_h_red<<<(HID * NB + 255) / 256, 256>>>(P1, S1B);

    // 5) S-term for layer 2: T2[b][n]
    t_small<HID><<<OUTF, 256>>>(S1B, W2, T2, OUTF);

    // 6) GEMM2: out = max_b lrelu(local(H1)@W2^T + T2 + b2) (fused agg + max)
    gemm_mma<HID / 2, OUTF, 1><<<dim3(OUTF / 128, NMB), 256, SMEM>>>(
        nullptr, H1P, W2h, b2, T2, nullptr, out);
}

// round 17
// speedup vs baseline: 1.1455x; 1.0479x over previous
#include <cuda_runtime.h>
#include <cuda_fp16.h>
#include <math.h>
#include <cstdint>

// ---------------- problem constants ----------------------------------------
#define NB    8
#define Cc    256
#define HW    961
#define Mrows 7688
#define MP    7808          // padded M = 61*128
#define HID   512
#define OUTF  256
#define NMB   122           // m-blocks of 64 in GEMM1 grid

// ---------------- scratch (device globals; zero-initialized) ----------------
__device__ float    g_S0  [NB * Cc];
__device__ uint32_t g_YP  [MP * (Cc / 2)];     // LOCAL agg, packed fp16x2 [m][k2]
__device__ uint32_t g_W1hP[HID * (Cc / 2)];
__device__ uint32_t g_W2hP[OUTF * (HID / 2)];
__device__ uint32_t g_H1P [MP * (HID / 2)];    // H1 packed fp16x2 [m][k2]
__device__ float    g_P1  [NMB * 2 * HID];     // per-mblock per-sample-slot column sums
__device__ float    g_S1B [NB * HID];          // per-sample sums [b][k]
__device__ float    g_T1  [NB * HID];          // S-term epilogue corrections
__device__ float    g_T2  [NB * OUTF];

// ---------------- helpers ----------------------------------------------------
__device__ __forceinline__ uint32_t smem_u32(const void* p) {
    uint32_t a;
    asm("{ .reg .u64 t; cvta.to.shared.u64 t, %1; cvt.u32.u64 %0, t; }"
        : "=r"(a) : "l"(p));
    return a;
}

__device__ __forceinline__ float dinv_of(int b) {
    int deg = (b == 0 || b == NB - 1) ? 963 : 964;
    return 1.0f / sqrtf((float)deg);
}

__device__ __forceinline__ uint32_t f16x2_pack(float v0, float v1) {
    __half2 h = __floats2half2_rn(v0, v1);
    return *(uint32_t*)&h;
}

// deterministic float atomic max (dst inited to -inf)
__device__ __forceinline__ void atomicMaxF(float* addr, float v) {
    if (v >= 0.f) atomicMax((int*)addr, __float_as_int(v));
    else          atomicMin((unsigned int*)addr, (unsigned int)__float_as_int(v));
}

#define MMA_F16(d, a0, a1, a2, a3, b0, b1) \
    asm volatile("mma.sync.aligned.m16n8k16.row.col.f32.f16.f16.f32 " \
                 "{%0,%1,%2,%3},{%4,%5,%6,%7},{%8,%9},{%0,%1,%2,%3};" \
                 : "+f"((d)[0]), "+f"((d)[1]), "+f"((d)[2]), "+f"((d)[3]) \
                 : "r"(a0), "r"(a1), "r"(a2), "r"(a3), "r"(b0), "r"(b1))

#define LDSM_X4(r0, r1, r2, r3, addr) \
    asm volatile("ldmatrix.sync.aligned.m8n8.x4.shared.b16 {%0,%1,%2,%3}, [%4];" \
                 : "=r"(r0), "=r"(r1), "=r"(r2), "=r"(r3) : "r"(addr))

#define CP_ASYNC16(dst32, src) \
    asm volatile("cp.async.cg.shared.global [%0], [%1], 16;" :: "r"(dst32), "l"(src))
#define CP_COMMIT()  asm volatile("cp.async.commit_group;" ::: "memory")
#define CP_WAIT1()   asm volatile("cp.async.wait_group 1;" ::: "memory")

// ---------------- fused prep kernel (one launch, 5 jobs) ----------------------
#define PREP_BLOCKS 3409
__global__ void prep_fused(const float* __restrict__ x,
                           const float* __restrict__ W1,
                           const float* __restrict__ W2,
                           float* __restrict__ S0,
                           uint32_t* __restrict__ YP,
                           uint32_t* __restrict__ W1h,
                           uint32_t* __restrict__ W2h,
                           float* __restrict__ out) {
    __shared__ float red[8];
    const int blk = blockIdx.x;
    const int tid = threadIdx.x;

    if (blk < 992) {
        int mblk = blk % 31, cq = blk / 31;
        int m = mblk * 256 + tid;
        if (m >= Mrows) return;
        int b = m / HW, p = m - b * HW;
        float db = dinv_of(b);
        float c0 = db * db;
        float cm = (b > 0)      ? db * dinv_of(b - 1) : 0.f;
        float cp = (b < NB - 1) ? db * dinv_of(b + 1) : 0.f;
        uint32_t w[4];
        #pragma unroll
        for (int j = 0; j < 4; j++) {
            float v2[2];
            #pragma unroll
            for (int e = 0; e < 2; e++) {
                int c = cq * 8 + j * 2 + e;
                size_t xi = (size_t)(b * Cc + c) * HW + p;
                float vv = c0 * __ldg(&x[xi]);
                if (b > 0)      vv += cm * __ldg(&x[xi - (size_t)Cc * HW]);
                if (b < NB - 1) vv += cp * __ldg(&x[xi + (size_t)Cc * HW]);
                v2[e] = vv;
            }
            w[j] = f16x2_pack(v2[0], v2[1]);
        }
        *(uint4*)(YP + (size_t)m * (Cc / 2) + cq * 4) = make_uint4(w[0], w[1], w[2], w[3]);
    } else if (blk < 3040) {
        int bc = blk - 992;
        const float* src = x + (size_t)bc * HW;
        float s = 0.f;
        for (int p = tid; p < HW; p += 256) s += src[p];
        #pragma unroll
        for (int off = 16; off; off >>= 1) s += __shfl_down_sync(0xffffffffu, s, off);
        if ((tid & 31) == 0) red[tid >> 5] = s;
        __syncthreads();
        if (tid < 8) {
            s = red[tid];
            #pragma unroll
            for (int off = 4; off; off >>= 1) s += __shfl_down_sync(0xffu, s, off);
            if (tid == 0) S0[bc] = s;
        }
    } else if (blk < 3168) {
        bool isW1 = blk < 3104;
        const float* W = isW1 ? W1 : W2;
        uint32_t* Wh = isW1 ? W1h : W2h;
        int base = ((blk - (isW1 ? 3040 : 3104)) * 256 + tid) * 4;
        float4 a = ((const float4*)W)[base / 2];
        float4 c = ((const float4*)W)[base / 2 + 1];
        Wh[base]     = f16x2_pack(a.x, a.y);
        Wh[base + 1] = f16x2_pack(a.z, a.w);
        Wh[base + 2] = f16x2_pack(c.x, c.y);
        Wh[base + 3] = f16x2_pack(c.z, c.w);
    } else {
        int i4 = (blk - 3168) * 256 + tid;
        if (i4 < OUTF * HW / 4) {
            float ninf = __int_as_float(0xFF800000);
            ((float4*)out)[i4] = make_float4(ninf, ninf, ninf, ninf);
        }
    }
}

// ---------------- tiny S-term GEMM: T[b][n] = c0_b * sum_k S[b,k] W[n,k] -----
template<int K>
__global__ void t_small(const float* __restrict__ S, const float* __restrict__ W,
                        float* __restrict__ T, int N) {
    int w = threadIdx.x >> 5, lane = threadIdx.x & 31;
    int idx = blockIdx.x * 8 + w;
    if (idx >= N * NB) return;
    int n = idx >> 3, b = idx & 7;
    float s = 0.f;
    #pragma unroll
    for (int k = lane; k < K; k += 32)
        s += __ldg(&S[b * K + k]) * __ldg(&W[n * K + k]);
    #pragma unroll
    for (int off = 16; off; off >>= 1) s += __shfl_down_sync(0xffffffffu, s, off);
    if (lane == 0) {
        float db = dinv_of(b);
        T[b * N + n] = db * db * s;
    }
}

// ---------------- fold P1 partials -> S1B[b][k]  (warp per output) ------------
__global__ void sum_h_red(const float* __restrict__ P1, float* __restrict__ S1B) {
    int w = threadIdx.x >> 5, lane = threadIdx.x & 31;
    int idx = blockIdx.x * 8 + w;                 // 0..4095, one warp each
    if (idx >= HID * NB) return;
    int k = idx >> 3, b = idx & 7;
    int mb0 = (b * HW) / 64;
    int mb1 = ((b + 1) * HW - 1) / 64;
    if (mb1 > NMB - 1) mb1 = NMB - 1;
    float s = 0.f;
    int mb = mb0 + lane;                          // lanes 0..16 active
    if (mb <= mb1) {
        int bl = (mb * 64) / HW;
        int sidx = b - bl;                        // 0 or 1
        s = __ldg(&P1[((size_t)mb * 2 + sidx) * HID + k]);
    }
    #pragma unroll
    for (int off = 16; off; off >>= 1) s += __shfl_down_sync(0xffffffffu, s, off);
    if (lane == 0) S1B[b * HID + k] = s;
}

// ---------------- fp16 mma.sync GEMM, 64x128 CTA, ldmatrix -------------------
// MODE 0: A from AP; epilogue -> pack H1P + per-CTA column-sum partials P1.
// MODE 1: A = local agg of H1P; epilogue -> atomicMax out.
// Both add TT[b][n] (S-term) + bias before lrelu.
template<int K2TOT, int NTOT, int MODE>
__global__ __launch_bounds__(256)
void gemm_mma(const uint32_t* __restrict__ AP,
              const uint32_t* __restrict__ H1P,
              const uint32_t* __restrict__ BhP,
              const float* __restrict__ bias, const float* __restrict__ TT,
              float* __restrict__ P1, void* __restrict__ OUTP) {
    extern __shared__ uint32_t smu[];
    constexpr int ROWW  = 20;
    constexpr int ATILE = 64 * ROWW;
    constexpr int BTILE = 128 * ROWW;
    constexpr int BUFW  = ATILE + BTILE;
    constexpr int NC    = K2TOT / 16;

    const int tid  = threadIdx.x;
    const int lane = tid & 31;
    const int wid  = tid >> 5;
    const int bm   = blockIdx.y * 64;
    const int bn   = blockIdx.x * 128;
    const int wm   = (wid & 1) * 32;
    const int wn   = (wid >> 1) * 32;
    const int g    = lane >> 2, tg = lane & 3;
    const uint32_t sb = smem_u32(smu);

    const int mat = lane >> 3, r8 = lane & 7;
    const int aoff0 = (wm + (mat & 1) * 8 + r8) * ROWW + (mat >> 1) * 4;
    const int aoff1 = aoff0 + 16 * ROWW;
    const int boff0 = ATILE + (wn + (mat >> 1) * 8 + r8) * ROWW + (mat & 1) * 4;
    const int boff1 = boff0 + 16 * ROWW;

    float acc[2][4][4];
    #pragma unroll
    for (int i = 0; i < 2; i++)
        #pragma unroll
        for (int j = 0; j < 4; j++)
            #pragma unroll
            for (int e = 0; e < 4; e++) acc[i][j][e] = 0.f;

    auto load_chunk = [&](int ch) {
        const int st   = ch & 1;
        const int k2_0 = ch * 16;
        const uint32_t bufb = sb + (uint32_t)(st * BUFW) * 4;
        #pragma unroll
        for (int i = 0; i < 2; i++) {
            int q   = tid + i * 256;
            int row = q >> 2, seg = q & 3;
            const uint32_t* src = BhP + (size_t)(bn + row) * K2TOT + k2_0 + seg * 4;
            uint32_t dst = bufb + (uint32_t)(ATILE + row * ROWW + seg * 4) * 4;
            CP_ASYNC16(dst, src);
        }
        if (MODE == 0) {
            int row = tid >> 2, seg = tid & 3;
            const uint32_t* src = AP + (size_t)(bm + row) * K2TOT + k2_0 + seg * 4;
            uint32_t dst = bufb + (uint32_t)(row * ROWW + seg * 4) * 4;
            CP_ASYNC16(dst, src);
        } else {
            uint32_t* bA = smu + st * BUFW;
            int mi = tid >> 2, seg = tid & 3;
            int m = bm + mi;
            int b = m / HW; if (b > NB - 1) b = NB - 1;
            float db = dinv_of(b);
            float c0 = db * db;
            bool hasm = (b > 0), hasp = (b < NB - 1);
            float cm = hasm ? db * dinv_of(b - 1) : 0.f;
            float cp = hasp ? db * dinv_of(b + 1) : 0.f;
            const uint32_t* hr = H1P + (size_t)m * K2TOT + k2_0 + seg * 4;
            uint4 h  = *(const uint4*)hr;
            uint4 hm = hasm ? *(const uint4*)(hr - (size_t)HW * K2TOT) : make_uint4(0,0,0,0);
            uint4 hp = hasp ? *(const uint4*)(hr + (size_t)HW * K2TOT) : make_uint4(0,0,0,0);
            const uint32_t* hw  = (const uint32_t*)&h;
            const uint32_t* hmw = (const uint32_t*)&hm;
            const uint32_t* hpw = (const uint32_t*)&hp;
            #pragma unroll
            for (int j = 0; j < 4; j++) {
                float2 f  = __half22float2(*(__half2*)&hw[j]);
                float2 fm = __half22float2(*(__half2*)&hmw[j]);
                float2 fp = __half22float2(*(__half2*)&hpw[j]);
                float v0 = c0 * f.x + cm * fm.x + cp * fp.x;
                float v1 = c0 * f.y + cm * fm.y + cp * fp.y;
                bA[mi * ROWW + seg * 4 + j] = f16x2_pack(v0, v1);
            }
        }
    };

    load_chunk(0);
    CP_COMMIT();

    for (int ch = 0; ch < NC; ch++) {
        if (ch + 1 < NC) load_chunk(ch + 1);
        CP_COMMIT();
        CP_WAIT1();
        __syncthreads();

        const uint32_t stb = sb + (uint32_t)((ch & 1) * BUFW) * 4;

        #pragma unroll
        for (int kk = 0; kk < 2; kk++) {
            const uint32_t kof = (uint32_t)(kk * 8) * 4;
            uint32_t a0[4], a1[4], b0[4], b1[4];
            LDSM_X4(a0[0], a0[1], a0[2], a0[3], stb + (uint32_t)aoff0 * 4 + kof);
            LDSM_X4(a1[0], a1[1], a1[2], a1[3], stb + (uint32_t)aoff1 * 4 + kof);
            LDSM_X4(b0[0], b0[1], b0[2], b0[3], stb + (uint32_t)boff0 * 4 + kof);
            LDSM_X4(b1[0], b1[1], b1[2], b1[3], stb + (uint32_t)boff1 * 4 + kof);
            MMA_F16(acc[0][0], a0[0], a0[1], a0[2], a0[3], b0[0], b0[1]);
            MMA_F16(acc[0][1], a0[0], a0[1], a0[2], a0[3], b0[2], b0[3]);
            MMA_F16(acc[0][2], a0[0], a0[1], a0[2], a0[3], b1[0], b1[1]);
            MMA_F16(acc[0][3], a0[0], a0[1], a0[2], a0[3], b1[2], b1[3]);
            MMA_F16(acc[1][0], a1[0], a1[1], a1[2], a1[3], b0[0], b0[1]);
            MMA_F16(acc[1][1], a1[0], a1[1], a1[2], a1[3], b0[2], b0[3]);
            MMA_F16(acc[1][2], a1[0], a1[1], a1[2], a1[3], b1[0], b1[1]);
            MMA_F16(acc[1][3], a1[0], a1[1], a1[2], a1[3], b1[2], b1[3]);
        }
        __syncthreads();
    }

    // ---------------- epilogue -----------------------------------------------
    const int b_lo_raw = bm / HW;
    const int b_lo = (b_lo_raw > NB - 1) ? NB - 1 : b_lo_raw;
    float sumS[2][8];
    #pragma unroll
    for (int s = 0; s < 2; s++)
        #pragma unroll
        for (int i = 0; i < 8; i++) sumS[s][i] = 0.f;

    #pragma unroll
    for (int mt = 0; mt < 2; mt++) {
        int m0 = bm + wm + mt * 16 + g;
        bool v0 = m0 < Mrows, v8 = (m0 + 8) < Mrows;
        int b0i = m0 / HW;       if (b0i > NB - 1) b0i = NB - 1;
        int b8i = (m0 + 8) / HW; if (b8i > NB - 1) b8i = NB - 1;
        const float* tt0 = TT + b0i * NTOT;
        const float* tt8 = TT + b8i * NTOT;
        int s0 = b0i - b_lo; if (s0 > 1) s0 = 1; if (s0 < 0) s0 = 0;
        int s8 = b8i - b_lo; if (s8 > 1) s8 = 1; if (s8 < 0) s8 = 0;
        #pragma unroll
        for (int nt = 0; nt < 4; nt++) {
            int n = bn + wn + nt * 8 + 2 * tg;
            float bb0 = __ldg(&bias[n]), bb1 = __ldg(&bias[n + 1]);
            float c0 = acc[mt][nt][0] + bb0 + __ldg(&tt0[n]);
            float c1 = acc[mt][nt][1] + bb1 + __ldg(&tt0[n + 1]);
            float c2 = acc[mt][nt][2] + bb0 + __ldg(&tt8[n]);
            float c3 = acc[mt][nt][3] + bb1 + __ldg(&tt8[n + 1]);
            c0 = c0 > 0.f ? c0 : 0.01f * c0;
            c1 = c1 > 0.f ? c1 : 0.01f * c1;
            c2 = c2 > 0.f ? c2 : 0.01f * c2;
            c3 = c3 > 0.f ? c3 : 0.01f * c3;
            if (MODE == 0) {
                uint32_t* H = (uint32_t*)OUTP;
                int n2 = n >> 1;
                if (v0) {
                    H[(size_t)m0 * (NTOT / 2) + n2] = f16x2_pack(c0, c1);
                    sumS[s0][nt * 2]     += c0;
                    sumS[s0][nt * 2 + 1] += c1;
                }
                if (v8) {
                    H[(size_t)(m0 + 8) * (NTOT / 2) + n2] = f16x2_pack(c2, c3);
                    sumS[s8][nt * 2]     += c2;
                    sumS[s8][nt * 2 + 1] += c3;
                }
            } else {
                float* out = (float*)OUTP;
                if (v0) {
                    int p = m0 - b0i * HW;
                    atomicMaxF(out + (size_t)n * HW + p, c0);
                    atomicMaxF(out + (size_t)(n + 1) * HW + p, c1);
                }
                if (v8) {
                    int p = m0 + 8 - b8i * HW;
                    atomicMaxF(out + (size_t)n * HW + p, c2);
                    atomicMaxF(out + (size_t)(n + 1) * HW + p, c3);
                }
            }
        }
    }

    if (MODE == 0) {
        #pragma unroll
        for (int off = 16; off >= 4; off >>= 1)
            #pragma unroll
            for (int s = 0; s < 2; s++)
                #pragma unroll
                for (int i = 0; i < 8; i++)
                    sumS[s][i] += __shfl_down_sync(0xffffffffu, sumS[s][i], off);
        float* sred = (float*)smu;
        __syncthreads();
        if (lane < 4) {
            #pragma unroll
            for (int s = 0; s < 2; s++)
                #pragma unroll
                for (int i = 0; i < 8; i++) {
                    int nl = (i >> 1) * 8 + 2 * lane + (i & 1);
                    sred[(wid * 2 + s) * 32 + nl] = sumS[s][i];
                }
        }
        __syncthreads();
        {
            int s  = tid >> 7;
            int nl = tid & 127;
            int wp = nl >> 5;
            float v = sred[((wp * 2 + 0) * 2 + s) * 32 + (nl & 31)]
                    + sred[((wp * 2 + 1) * 2 + s) * 32 + (nl & 31)];
            P1[((size_t)blockIdx.y * 2 + s) * NTOT + bn + nl] = v;
        }
    }
}

// ---------------- launcher ----------------------------------------------------
extern "C" void kernel_launch(void* const* d_in, const int* in_sizes, int n_in,
                              void* d_out, int out_size) {
    const float* x  = (const float*)d_in[0];
    const float* W1 = (const float*)d_in[1];
    const float* b1 = (const float*)d_in[2];
    const float* W2 = (const float*)d_in[3];
    const float* b2 = (const float*)d_in[4];
    float* out = (float*)d_out;

    float *S0, *P1, *S1B, *T1, *T2;
    uint32_t *YP, *W1h, *W2h, *H1P;
    cudaGetSymbolAddress((void**)&S0,  g_S0);
    cudaGetSymbolAddress((void**)&YP,  g_YP);
    cudaGetSymbolAddress((void**)&W1h, g_W1hP);
    cudaGetSymbolAddress((void**)&W2h, g_W2hP);
    cudaGetSymbolAddress((void**)&H1P, g_H1P);
    cudaGetSymbolAddress((void**)&P1,  g_P1);
    cudaGetSymbolAddress((void**)&S1B, g_S1B);
    cudaGetSymbolAddress((void**)&T1,  g_T1);
    cudaGetSymbolAddress((void**)&T2,  g_T2);

    constexpr int SMEM = 2 * 3840 * 4;
    cudaFuncSetAttribute(gemm_mma<Cc / 2,  HID,  0>,
                         cudaFuncAttributeMaxDynamicSharedMemorySize, SMEM);
    cudaFuncSetAttribute(gemm_mma<HID / 2, OUTF, 1>,
                         cudaFuncAttributeMaxDynamicSharedMemorySize, SMEM);

    // 1) fused prep: local agg -> YP, sums -> S0, W packs, out = -inf
    prep_fused<<<PREP_BLOCKS, 256>>>(x, W1, W2, S0, YP, W1h, W2h, out);

    // 2) S-term for layer 1: T1[b][n] (fp32, exact)
    t_small<Cc><<<HID, 256>>>(S0, W1, T1, HID);

    // 3) GEMM1: H1P = pack(lrelu(local@W1^T + T1 + b1)); P1 column-sum partials
    gemm_mma<Cc / 2, HID, 0><<<dim3(HID / 128, NMB), 256, SMEM>>>(
        YP, nullptr, W1h, b1, T1, P1, H1P);

    // 4) fold partials -> S1B (warp per output, 128 blocks)
    sum_h_red<<<(HID * NB + 7) / 8, 256>>>(P1, S1B);

    // 5) S-term for layer 2: T2[b][n]
    t_small<HID><<<OUTF, 256>>>(S1B, W2, T2, OUTF);

    // 6) GEMM2: out = max_b lrelu(local(H1)@W2^T + T2 + b2) (fused agg + max)
    gemm_mma<HID / 2, OUTF, 1><<<dim3(OUTF / 128, NMB), 256, SMEM>>>(
        nullptr, H1P, W2h, b2, T2, nullptr, out);
}